// round 8
// baseline (speedup 1.0000x reference)
#include <cuda_runtime.h>
#include <math_constants.h>

// Problem dims
#define BATCH 64
#define DIM   768
#define MEM   2048
#define NCLS  1000

#define EC    48               // e-chunk per score unit (DIM/EC = 16)
#define NEC   (DIM / EC)
#define KC    32               // gemm k-chunk
#define NJT   12               // gemm j-tiles of 64
#define GEMM_UNITS (NJT * (DIM / KC))   // 288
#define SCORE_UNITS (2 * NEC * BATCH)   // 2048

#define CTAS_PER_SM 8
#define GRIDN (CTAS_PER_SM * 148)       // 1184: full wave-1, co-resident, 100% occ
#define NTHR  256

// Scratch (allocation-free)
__device__ float g_q[BATCH * DIM];
__device__ float g_t[BATCH * DIM];
__device__ float g_scores[BATCH * MEM];
__device__ unsigned g_bar[4];   // monotonic barrier counters (never reset)
__device__ unsigned g_ticket;   // score work ticket (reset each launch in P0)

// ---------------------------------------------------------------------------
// Grid-wide barrier for a co-resident grid. Monotonic counter: release when
// count reaches (gen+1)*GRIDN. No reset needed across graph replays.
// ---------------------------------------------------------------------------
__device__ __forceinline__ void grid_barrier(unsigned* ctr) {
    __threadfence();
    __syncthreads();
    if (threadIdx.x == 0) {
        const unsigned t = atomicAdd(ctr, 1u);
        const unsigned target = (t / GRIDN + 1u) * GRIDN;
        while (*(volatile unsigned*)ctr < target) __nanosleep(128);
    }
    __syncthreads();
}

// ---------------------------------------------------------------------------
// GEMM phase: C[64,768] += A[64,768] @ W[768,768], split-K atomics.
// 288 units = 12 j-tiles(64) x 24 k-chunks(32); unit = blockIdx.x (<288).
// Thread (jv 0..15, bg 0..15): 4 j (float4 W) x 4 b -> 16 accumulators,
// register-lean (fits the 32-reg budget imposed by 8 CTAs/SM).
// ---------------------------------------------------------------------------
__device__ void gemm_phase(const float* __restrict__ A,
                           const float* __restrict__ W,
                           float* __restrict__ C, bool viaL2) {
    const int u = blockIdx.x;
    if (u < GEMM_UNITS) {
        const int jt = u % NJT;
        const int k0 = (u / NJT) * KC;

        __shared__ float xs[KC][BATCH + 1];

        for (int i = threadIdx.x; i < BATCH * KC; i += NTHR) {
            const int b = i >> 5;
            const int d = i & 31;
            xs[d][b] = viaL2 ? __ldcg(&A[b * DIM + k0 + d]) : A[b * DIM + k0 + d];
        }
        __syncthreads();

        const int jv = threadIdx.x & 15;
        const int bg = threadIdx.x >> 4;     // 16 groups of 4 b
        const int j  = jt * 64 + jv * 4;

        float acc[4][4];
        #pragma unroll
        for (int bb = 0; bb < 4; bb++)
            #pragma unroll
            for (int jj = 0; jj < 4; jj++) acc[bb][jj] = 0.0f;

        #pragma unroll 4
        for (int d = 0; d < KC; d++) {
            const float4 w = *(const float4*)&W[(size_t)(k0 + d) * DIM + j];
            #pragma unroll
            for (int bb = 0; bb < 4; bb++) {
                const float xv = xs[d][bg * 4 + bb];
                acc[bb][0] = fmaf(xv, w.x, acc[bb][0]);
                acc[bb][1] = fmaf(xv, w.y, acc[bb][1]);
                acc[bb][2] = fmaf(xv, w.z, acc[bb][2]);
                acc[bb][3] = fmaf(xv, w.w, acc[bb][3]);
            }
        }

        #pragma unroll
        for (int bb = 0; bb < 4; bb++) {
            const int b = bg * 4 + bb;
            atomicAdd(&C[b * DIM + j + 0], acc[bb][0]);
            atomicAdd(&C[b * DIM + j + 1], acc[bb][1]);
            atomicAdd(&C[b * DIM + j + 2], acc[bb][2]);
            atomicAdd(&C[b * DIM + j + 3], acc[bb][3]);
        }
    }
}

// ---------------------------------------------------------------------------
// Score phase (dominant, HBM-bound): scores[b,m] += sum_e t[b,e]*mem[b,e,m].
// 2048 units = (2 m-tiles of 1024) x 16 e-chunks x 64 b, pulled dynamically
// via a global ticket (work stealing -> balanced tail).
// ---------------------------------------------------------------------------
__device__ void score_phase(const float* __restrict__ mem) {
    __shared__ float ts[EC];
    __shared__ unsigned sh_u;

    while (true) {
        if (threadIdx.x == 0) sh_u = atomicAdd(&g_ticket, 1u);
        __syncthreads();
        const unsigned u = sh_u;
        if (u >= SCORE_UNITS) break;   // uniform across block

        const int b  = u & 63;
        const int ey = (u >> 6) & 15;
        const int mt = u >> 10;
        const int e0 = ey * EC;

        if (threadIdx.x < EC) ts[threadIdx.x] = __ldcg(&g_t[b * DIM + e0 + threadIdx.x]);
        __syncthreads();

        const int m = mt * 1024 + threadIdx.x * 4;
        const float4* mp = (const float4*)(mem + (size_t)b * DIM * MEM
                                               + (size_t)e0 * MEM + m);

        float ax = 0.f, ay = 0.f, az = 0.f, aw = 0.f;
        #pragma unroll 8
        for (int e = 0; e < EC; e++) {
            const float4 v = __ldcs(&mp[(size_t)e * (MEM / 4)]);
            const float w = ts[e];
            ax = fmaf(w, v.x, ax);
            ay = fmaf(w, v.y, ay);
            az = fmaf(w, v.z, az);
            aw = fmaf(w, v.w, aw);
        }

        float* sp = &g_scores[b * MEM + m];
        atomicAdd(sp + 0, ax);
        atomicAdd(sp + 1, ay);
        atomicAdd(sp + 2, az);
        atomicAdd(sp + 3, aw);
        __syncthreads();   // ts / sh_u safe for next unit
    }
}

// ---------------------------------------------------------------------------
// Epilogue phase: blocks 0..63, one batch row each. leaky-relu + scatter into
// shared logits[1000] (smem atomics), softmax, write out.
// ---------------------------------------------------------------------------
__device__ void epilogue_phase(const int* __restrict__ lab32,
                               float* __restrict__ out) {
    const int b = blockIdx.x;
    const int tid = threadIdx.x;

    __shared__ float logits[NCLS];
    __shared__ float red[8];
    __shared__ int   sh_is64;

    for (int i = tid; i < NCLS; i += NTHR) logits[i] = 0.0f;
    if (tid == 0) {
        int any = 0;
        #pragma unroll
        for (int k = 0; k < 32; k++) any |= lab32[2 * k + 1];
        sh_is64 = (any == 0) ? 1 : 0;
    }
    __syncthreads();
    const int is64 = sh_is64;

    for (int i = tid; i < MEM; i += NTHR) {
        const size_t idx = (size_t)b * MEM + i;
        const float s = __ldcg(&g_scores[idx]);
        const float sv = (s >= 0.0f) ? s : 0.01f * s;
        int lab = is64 ? lab32[2 * idx] : lab32[idx];
        lab = min(max(lab, 0), NCLS - 1);
        atomicAdd(&logits[lab], sv);
    }
    __syncthreads();

    // --- max ---
    float mx = -CUDART_INF_F;
    for (int i = tid; i < NCLS; i += NTHR) mx = fmaxf(mx, logits[i]);
    #pragma unroll
    for (int o = 16; o > 0; o >>= 1) mx = fmaxf(mx, __shfl_xor_sync(0xffffffffu, mx, o));
    if ((tid & 31) == 0) red[tid >> 5] = mx;
    __syncthreads();
    if (tid < 32) {
        float v = (tid < 8) ? red[tid] : -CUDART_INF_F;
        #pragma unroll
        for (int o = 4; o > 0; o >>= 1) v = fmaxf(v, __shfl_xor_sync(0xffffffffu, v, o));
        if (tid == 0) red[0] = v;
    }
    __syncthreads();
    mx = red[0];
    __syncthreads();

    // --- exp + sum ---
    float sum = 0.0f;
    for (int i = tid; i < NCLS; i += NTHR) {
        const float e = __expf(logits[i] - mx);
        logits[i] = e;
        sum += e;
    }
    #pragma unroll
    for (int o = 16; o > 0; o >>= 1) sum += __shfl_xor_sync(0xffffffffu, sum, o);
    if ((tid & 31) == 0) red[tid >> 5] = sum;
    __syncthreads();
    if (tid < 32) {
        float v = (tid < 8) ? red[tid] : 0.0f;
        #pragma unroll
        for (int o = 4; o > 0; o >>= 1) v += __shfl_xor_sync(0xffffffffu, v, o);
        if (tid == 0) red[0] = v;
    }
    __syncthreads();
    const float inv = 1.0f / red[0];

    for (int i = tid; i < NCLS; i += NTHR) out[b * NCLS + i] = logits[i] * inv;
}

// ---------------------------------------------------------------------------
// Single persistent kernel, 8 CTAs/SM (<=32 regs): P0 zero -> P1 q=x@W_K ->
// P2 t=q@W_Q -> P3 score -> P4 epilogue, with software grid barriers.
// ---------------------------------------------------------------------------
__global__ void __launch_bounds__(NTHR, CTAS_PER_SM) fused_all(
    const float* __restrict__ x, const float* __restrict__ mem,
    const int* __restrict__ lab32,
    const float* __restrict__ W_Q, const float* __restrict__ W_K,
    float* __restrict__ out)
{
    // P0: zero scratch + reset ticket
    {
        const float4 z = make_float4(0.f, 0.f, 0.f, 0.f);
        const int i = blockIdx.x * NTHR + threadIdx.x;
        if (i < BATCH * DIM / 4) {
            ((float4*)g_q)[i] = z;
            ((float4*)g_t)[i] = z;
        }
        if (i < BATCH * MEM / 4) ((float4*)g_scores)[i] = z;
        if (blockIdx.x == 0 && threadIdx.x == 0) g_ticket = 0u;
    }
    grid_barrier(&g_bar[0]);

    gemm_phase(x, W_K, g_q, false);     // P1: q = x @ W_K
    grid_barrier(&g_bar[1]);

    gemm_phase(g_q, W_Q, g_t, true);    // P2: t = q @ W_Q
    grid_barrier(&g_bar[2]);

    score_phase(mem);                   // P3: dominant streaming phase
    grid_barrier(&g_bar[3]);

    if (blockIdx.x < BATCH) epilogue_phase(lab32, out);  // P4
}

// ---------------------------------------------------------------------------
// Launch: ONE kernel. Inputs mapped by element count: x 49152, mem 100663296,
// labels 131072, W_Q / W_K 589824 each (W_Q first). Output: f32[64,1000].
// ---------------------------------------------------------------------------
extern "C" void kernel_launch(void* const* d_in, const int* in_sizes, int n_in,
                              void* d_out, int out_size) {
    const float* x   = nullptr;
    const float* mem = nullptr;
    const int* labs  = nullptr;
    const float* W_Q = nullptr;
    const float* W_K = nullptr;

    for (int i = 0; i < n_in; i++) {
        const int sz = in_sizes[i];
        if (sz == BATCH * DIM)            x    = (const float*)d_in[i];
        else if (sz == BATCH * DIM * MEM) mem  = (const float*)d_in[i];
        else if (sz == BATCH * MEM)       labs = (const int*)d_in[i];
        else if (sz == DIM * DIM) {
            if (!W_Q) W_Q = (const float*)d_in[i];
            else      W_K = (const float*)d_in[i];
        }
    }
    float* out = (float*)d_out;

    fused_all<<<GRIDN, NTHR>>>(x, mem, labs, W_Q, W_K, out);
}

// round 9
// speedup vs baseline: 1.1311x; 1.1311x over previous
#include <cuda_runtime.h>
#include <math_constants.h>

// Problem dims
#define BATCH 64
#define DIM   768
#define MEM   2048
#define NCLS  1000

#define EC    48               // e-chunk per score block (DIM/EC = 16)
#define NEC   (DIM / EC)
#define KC    16               // gemm k-chunk
#define NJT   6                // gemm j-tiles of 128
#define PREP_GRID (NJT * (DIM / KC))   // 288 = exactly the gemm unit count

// Scratch (allocation-free)
__device__ float g_q[BATCH * DIM];
__device__ float g_t[BATCH * DIM];
__device__ float g_scores[BATCH * MEM];
__device__ unsigned g_bar[2];   // monotonic barrier counters (never reset)

// ---------------------------------------------------------------------------
// Grid barrier for a small, guaranteed co-resident grid (288 blocks).
// Monotonic counter: release when count reaches (gen+1)*PREP_GRID.
// No reset needed across graph replays.
// ---------------------------------------------------------------------------
__device__ __forceinline__ void grid_barrier(unsigned* ctr) {
    __threadfence();
    __syncthreads();
    if (threadIdx.x == 0) {
        const unsigned t = atomicAdd(ctr, 1u);
        const unsigned target = (t / PREP_GRID + 1u) * PREP_GRID;
        while (*(volatile unsigned*)ctr < target) __nanosleep(64);
    }
    __syncthreads();
}

// ---------------------------------------------------------------------------
// GEMM phase: C[64,768] += A[64,768] @ W[768,768], split-K atomics.
// 288 units = 6 j-tiles(128) x 48 k-chunks(16); unit = blockIdx.x.
// Thread: 4 consecutive j (float4 W) x 8 b (smem broadcast) = 32 accumulators.
// viaL2: g_q was written by same-kernel atomics on other SMs -> __ldcg.
// ---------------------------------------------------------------------------
__device__ void gemm_phase(const float* __restrict__ A,
                           const float* __restrict__ W,
                           float* __restrict__ C, bool viaL2) {
    const int u  = blockIdx.x;
    const int jt = u % NJT;
    const int k0 = (u / NJT) * KC;

    __shared__ float xs[KC][BATCH + 1];

    for (int i = threadIdx.x; i < BATCH * KC; i += 256) {
        const int b = i >> 4;          // i / 16
        const int d = i & (KC - 1);    // i % 16
        xs[d][b] = viaL2 ? __ldcg(&A[b * DIM + k0 + d]) : A[b * DIM + k0 + d];
    }
    __syncthreads();

    const int jv = threadIdx.x & 31;
    const int bg = threadIdx.x >> 5;
    const int j  = jt * 128 + jv * 4;

    float acc[8][4];
    #pragma unroll
    for (int bb = 0; bb < 8; bb++)
        #pragma unroll
        for (int jj = 0; jj < 4; jj++) acc[bb][jj] = 0.0f;

    #pragma unroll
    for (int d = 0; d < KC; d++) {
        const float4 w = *(const float4*)&W[(size_t)(k0 + d) * DIM + j];
        #pragma unroll
        for (int bb = 0; bb < 8; bb++) {
            const float xv = xs[d][bg * 8 + bb];
            acc[bb][0] = fmaf(xv, w.x, acc[bb][0]);
            acc[bb][1] = fmaf(xv, w.y, acc[bb][1]);
            acc[bb][2] = fmaf(xv, w.z, acc[bb][2]);
            acc[bb][3] = fmaf(xv, w.w, acc[bb][3]);
        }
    }

    #pragma unroll
    for (int bb = 0; bb < 8; bb++) {
        const int b = bg * 8 + bb;
        atomicAdd(&C[b * DIM + j + 0], acc[bb][0]);
        atomicAdd(&C[b * DIM + j + 1], acc[bb][1]);
        atomicAdd(&C[b * DIM + j + 2], acc[bb][2]);
        atomicAdd(&C[b * DIM + j + 3], acc[bb][3]);
    }
    __syncthreads();   // xs reusable by next phase
}

// ---------------------------------------------------------------------------
// Prep kernel (replaces zero + gemm1 + gemm2 = 3 launches):
// P0 zero scratch -> barrier -> P1 q = x@W_K -> barrier -> P2 t = q@W_Q.
// 288 blocks x 256 threads, guaranteed co-resident (>=4 CTAs/SM capacity).
// ---------------------------------------------------------------------------
__global__ void __launch_bounds__(256) prep_kernel(
    const float* __restrict__ x,
    const float* __restrict__ W_Q, const float* __restrict__ W_K)
{
    {
        const float4 z = make_float4(0.f, 0.f, 0.f, 0.f);
        const int i = blockIdx.x * 256 + threadIdx.x;
        if (i < BATCH * DIM / 4) {
            ((float4*)g_q)[i] = z;
            ((float4*)g_t)[i] = z;
        }
        if (i < BATCH * MEM / 4) ((float4*)g_scores)[i] = z;
    }
    grid_barrier(&g_bar[0]);

    gemm_phase(x, W_K, g_q, false);    // P1: q = x @ W_K
    grid_barrier(&g_bar[1]);

    gemm_phase(g_q, W_Q, g_t, true);   // P2: t = q @ W_Q
}

// ---------------------------------------------------------------------------
// Dominant kernel (UNCHANGED from the proven 62.4us config):
// scores[b,m] += sum_{e in chunk} t[b,e]*mem[b,e,m]. Streams 402 MB once.
// grid = (2, 16, 64) = 2048 blocks x 256 threads, regs<=32 -> 8 CTAs/SM.
// PDL: address setup pre-sync; g_t/g_scores touched only post-sync.
// ---------------------------------------------------------------------------
__global__ void __launch_bounds__(256) score_partial(const float* __restrict__ mem) {
    const int b  = blockIdx.z;
    const int e0 = blockIdx.y * EC;
    const int m  = blockIdx.x * 1024 + threadIdx.x * 4;
    const float4* mp = (const float4*)(mem + (size_t)b * DIM * MEM
                                           + (size_t)e0 * MEM + m);

    cudaGridDependencySynchronize();   // prep_kernel fully complete

    __shared__ float ts[EC];
    if (threadIdx.x < EC) ts[threadIdx.x] = g_t[b * DIM + e0 + threadIdx.x];
    __syncthreads();

    float ax = 0.f, ay = 0.f, az = 0.f, aw = 0.f;
    #pragma unroll 8
    for (int e = 0; e < EC; e++) {
        const float4 v = __ldcs(&mp[(size_t)e * (MEM / 4)]);
        const float w = ts[e];  // warp-uniform broadcast
        ax = fmaf(w, v.x, ax);
        ay = fmaf(w, v.y, ay);
        az = fmaf(w, v.z, az);
        aw = fmaf(w, v.w, aw);
    }

    float* sp = &g_scores[b * MEM + m];
    atomicAdd(sp + 0, ax);
    atomicAdd(sp + 1, ay);
    atomicAdd(sp + 2, az);
    atomicAdd(sp + 3, aw);
    cudaTriggerProgrammaticLaunchCompletion();
}

// ---------------------------------------------------------------------------
// Fused epilogue: leaky-relu(scores) scattered into shared logits[1000]
// (smem atomics), softmax, write out. 64 blocks x 256 threads.
// PDL: logits zero + label-dtype detect pre-sync (overlaps score tail).
// ---------------------------------------------------------------------------
__global__ void __launch_bounds__(256) epilogue(const int* __restrict__ lab32,
                                                float* __restrict__ out) {
    const int b = blockIdx.x;
    const int tid = threadIdx.x;

    __shared__ float logits[NCLS];
    __shared__ float red[8];
    __shared__ int   sh_is64;

    for (int i = tid; i < NCLS; i += 256) logits[i] = 0.0f;
    if (tid == 0) {
        int any = 0;
        #pragma unroll
        for (int k = 0; k < 32; k++) any |= lab32[2 * k + 1];
        sh_is64 = (any == 0) ? 1 : 0;   // int64 labels in [0,1000): odd words 0
    }
    __syncthreads();
    const int is64 = sh_is64;

    cudaGridDependencySynchronize();   // g_scores complete

    for (int i = tid; i < MEM; i += 256) {
        const size_t idx = (size_t)b * MEM + i;
        const float s = g_scores[idx];
        const float sv = (s >= 0.0f) ? s : 0.01f * s;
        int lab = is64 ? lab32[2 * idx] : lab32[idx];
        lab = min(max(lab, 0), NCLS - 1);
        atomicAdd(&logits[lab], sv);
    }
    __syncthreads();

    // --- max ---
    float mx = -CUDART_INF_F;
    for (int i = tid; i < NCLS; i += 256) mx = fmaxf(mx, logits[i]);
    #pragma unroll
    for (int o = 16; o > 0; o >>= 1) mx = fmaxf(mx, __shfl_xor_sync(0xffffffffu, mx, o));
    if ((tid & 31) == 0) red[tid >> 5] = mx;
    __syncthreads();
    if (tid < 32) {
        float v = (tid < 8) ? red[tid] : -CUDART_INF_F;
        #pragma unroll
        for (int o = 4; o > 0; o >>= 1) v = fmaxf(v, __shfl_xor_sync(0xffffffffu, v, o));
        if (tid == 0) red[0] = v;
    }
    __syncthreads();
    mx = red[0];
    __syncthreads();

    // --- exp + sum ---
    float sum = 0.0f;
    for (int i = tid; i < NCLS; i += 256) {
        const float e = __expf(logits[i] - mx);
        logits[i] = e;
        sum += e;
    }
    #pragma unroll
    for (int o = 16; o > 0; o >>= 1) sum += __shfl_xor_sync(0xffffffffu, sum, o);
    if ((tid & 31) == 0) red[tid >> 5] = sum;
    __syncthreads();
    if (tid < 32) {
        float v = (tid < 8) ? red[tid] : 0.0f;
        #pragma unroll
        for (int o = 4; o > 0; o >>= 1) v += __shfl_xor_sync(0xffffffffu, v, o);
        if (tid == 0) red[0] = v;
    }
    __syncthreads();
    const float inv = 1.0f / red[0];

    for (int i = tid; i < NCLS; i += 256) out[b * NCLS + i] = logits[i] * inv;
}

// ---------------------------------------------------------------------------
// Launch (3 nodes): prep (zero+gemm1+gemm2 with internal barriers) ->
// score (PDL) -> epilogue (PDL). prep launches plainly so it fully serializes
// with the previous replay's epilogue (which reads g_scores that prep zeroes).
// Inputs mapped by element count: x 49152, mem 100663296, labels 131072,
// W_Q / W_K 589824 each (W_Q first).  Output: f32[64,1000].
// ---------------------------------------------------------------------------
template <typename... Args>
static inline void launch_pdl(void (*kern)(Args...), dim3 grid, dim3 block,
                              Args... args) {
    cudaLaunchConfig_t cfg = {};
    cfg.gridDim = grid;
    cfg.blockDim = block;
    cfg.dynamicSmemBytes = 0;
    cfg.stream = 0;
    cudaLaunchAttribute attr[1];
    attr[0].id = cudaLaunchAttributeProgrammaticStreamSerialization;
    attr[0].val.programmaticStreamSerializationAllowed = 1;
    cfg.attrs = attr;
    cfg.numAttrs = 1;
    cudaLaunchKernelEx(&cfg, kern, args...);
}

extern "C" void kernel_launch(void* const* d_in, const int* in_sizes, int n_in,
                              void* d_out, int out_size) {
    const float* x   = nullptr;
    const float* mem = nullptr;
    const int* labs  = nullptr;
    const float* W_Q = nullptr;
    const float* W_K = nullptr;

    for (int i = 0; i < n_in; i++) {
        const int sz = in_sizes[i];
        if (sz == BATCH * DIM)            x    = (const float*)d_in[i];
        else if (sz == BATCH * DIM * MEM) mem  = (const float*)d_in[i];
        else if (sz == BATCH * MEM)       labs = (const int*)d_in[i];
        else if (sz == DIM * DIM) {
            if (!W_Q) W_Q = (const float*)d_in[i];
            else      W_K = (const float*)d_in[i];
        }
    }
    float* out = (float*)d_out;

    prep_kernel<<<PREP_GRID, 256>>>(x, W_Q, W_K);
    launch_pdl(score_partial, dim3(2, NEC, BATCH), dim3(256), mem);
    launch_pdl(epilogue, dim3(BATCH), dim3(256), labs, out);
}

// round 10
// speedup vs baseline: 1.1386x; 1.0067x over previous
#include <cuda_runtime.h>
#include <math_constants.h>

// Problem dims
#define BATCH 64
#define DIM   768
#define MEM   2048
#define NCLS  1000

#define EC    48               // e-chunk per score block (DIM/EC = 16)
#define NEC   (DIM / EC)

#define KCG   96               // gemm k-chunk
#define NKC   (DIM / KCG)      // 8 k-chunks
#define NJT   12               // gemm j-tiles of 64
#define GEMM_BLOCKS (NJT * NKC)        // 96
#define ZERO_BLOCKS 32                 // zero g_scores alongside gemm1

// Scratch (allocation-free). Split-K partials written by plain stores;
// consumers sum them. Only g_scores needs zeroing (score-phase atomics).
__device__ float g_qp[NKC * BATCH * DIM];   // q partials, 1.5 MB
__device__ float g_tp[NKC * BATCH * DIM];   // t partials, 1.5 MB
__device__ float g_scores[BATCH * MEM];

// ---------------------------------------------------------------------------
// GEMM with split-K partials (no atomics, no zero, no barriers):
// out[kc][b][j] = sum_{d in chunk kc} A[b,d] * W[d,j].
// 96 gemm blocks = 12 j-tiles(64) x 8 k-chunks(96); 256 threads.
// Thread (jv 0..15, bg 0..15): 4 j (float4 W) x 4 b -> 16 accumulators.
// stage 0: A = x (direct); blocks 96..127 zero g_scores instead.
// stage 1: A[b,d] = sum_p g_qp[p][b][d] (8 partials, L2-resident).
// ---------------------------------------------------------------------------
__global__ void __launch_bounds__(256) gemm_partial(const float* __restrict__ x,
                                                    const float* __restrict__ W,
                                                    int stage) {
    if (stage != 0) cudaGridDependencySynchronize();   // g_qp complete

    const int u = blockIdx.x;
    if (u >= GEMM_BLOCKS) {
        // gemm1 ride-along: zero g_scores (disjoint from gemm work)
        const int i = (u - GEMM_BLOCKS) * 256 + threadIdx.x;
        const int n4 = BATCH * MEM / 4;
        const float4 z = make_float4(0.f, 0.f, 0.f, 0.f);
        for (int k = i; k < n4; k += ZERO_BLOCKS * 256)
            ((float4*)g_scores)[k] = z;
        return;
    }

    const int jt = u % NJT;
    const int kc = u / NJT;
    const int k0 = kc * KCG;

    __shared__ float xs[KCG][BATCH + 1];

    if (stage == 0) {
        for (int i = threadIdx.x; i < BATCH * KCG; i += 256) {
            const int b = i / KCG;
            const int d = i - b * KCG;
            xs[d][b] = x[b * DIM + k0 + d];
        }
    } else {
        for (int i = threadIdx.x; i < BATCH * KCG; i += 256) {
            const int b = i / KCG;
            const int d = i - b * KCG;
            float s = 0.0f;
            #pragma unroll
            for (int p = 0; p < NKC; p++)
                s += g_qp[((size_t)p * BATCH + b) * DIM + k0 + d];
            xs[d][b] = s;
        }
    }
    __syncthreads();

    const int jv = threadIdx.x & 15;     // 16 j-vec positions (x4 = 64 j)
    const int bg = threadIdx.x >> 4;     // 16 b-groups of 4
    const int j  = jt * 64 + jv * 4;

    float acc[4][4];
    #pragma unroll
    for (int bb = 0; bb < 4; bb++)
        #pragma unroll
        for (int jj = 0; jj < 4; jj++) acc[bb][jj] = 0.0f;

    #pragma unroll 4
    for (int d = 0; d < KCG; d++) {
        const float4 w = *(const float4*)&W[(size_t)(k0 + d) * DIM + j];
        #pragma unroll
        for (int bb = 0; bb < 4; bb++) {
            const float xv = xs[d][bg * 4 + bb];
            acc[bb][0] = fmaf(xv, w.x, acc[bb][0]);
            acc[bb][1] = fmaf(xv, w.y, acc[bb][1]);
            acc[bb][2] = fmaf(xv, w.z, acc[bb][2]);
            acc[bb][3] = fmaf(xv, w.w, acc[bb][3]);
        }
    }

    float* outp = (stage == 0) ? g_qp : g_tp;
    #pragma unroll
    for (int bb = 0; bb < 4; bb++) {
        const int b = bg * 4 + bb;
        *(float4*)&outp[((size_t)kc * BATCH + b) * DIM + j] =
            make_float4(acc[bb][0], acc[bb][1], acc[bb][2], acc[bb][3]);
    }
}

// ---------------------------------------------------------------------------
// Dominant kernel (proven ~62.4us config): scores[b,m] += sum_e t[b,e]*mem[..].
// Streams 402 MB once. grid = (2, 16, 64) = 2048 blocks x 256 threads.
// ts[e] = sum of the 8 t-partials (tiny L2 prologue).
// ---------------------------------------------------------------------------
__global__ void __launch_bounds__(256) score_partial(const float* __restrict__ mem) {
    const int b  = blockIdx.z;
    const int e0 = blockIdx.y * EC;
    const int m  = blockIdx.x * 1024 + threadIdx.x * 4;
    const float4* mp = (const float4*)(mem + (size_t)b * DIM * MEM
                                           + (size_t)e0 * MEM + m);

    cudaGridDependencySynchronize();   // g_tp + zeroed g_scores complete

    __shared__ float ts[EC];
    if (threadIdx.x < EC) {
        float s = 0.0f;
        #pragma unroll
        for (int p = 0; p < NKC; p++)
            s += g_tp[((size_t)p * BATCH + b) * DIM + e0 + threadIdx.x];
        ts[threadIdx.x] = s;
    }
    __syncthreads();

    float ax = 0.f, ay = 0.f, az = 0.f, aw = 0.f;
    #pragma unroll 8
    for (int e = 0; e < EC; e++) {
        const float4 v = __ldcs(&mp[(size_t)e * (MEM / 4)]);
        const float w = ts[e];  // warp-uniform broadcast
        ax = fmaf(w, v.x, ax);
        ay = fmaf(w, v.y, ay);
        az = fmaf(w, v.z, az);
        aw = fmaf(w, v.w, aw);
    }

    float* sp = &g_scores[b * MEM + m];
    atomicAdd(sp + 0, ax);
    atomicAdd(sp + 1, ay);
    atomicAdd(sp + 2, az);
    atomicAdd(sp + 3, aw);
    cudaTriggerProgrammaticLaunchCompletion();
}

// ---------------------------------------------------------------------------
// Fused epilogue: leaky-relu(scores) scattered into shared logits[1000]
// (smem atomics), softmax, write out. 64 blocks x 256 threads.
// PDL: logits zero + label-dtype detect pre-sync (overlaps score tail).
// ---------------------------------------------------------------------------
__global__ void __launch_bounds__(256) epilogue(const int* __restrict__ lab32,
                                                float* __restrict__ out) {
    const int b = blockIdx.x;
    const int tid = threadIdx.x;

    __shared__ float logits[NCLS];
    __shared__ float red[8];
    __shared__ int   sh_is64;

    for (int i = tid; i < NCLS; i += 256) logits[i] = 0.0f;
    if (tid == 0) {
        int any = 0;
        #pragma unroll
        for (int k = 0; k < 32; k++) any |= lab32[2 * k + 1];
        sh_is64 = (any == 0) ? 1 : 0;   // int64 labels in [0,1000): odd words 0
    }
    __syncthreads();
    const int is64 = sh_is64;

    cudaGridDependencySynchronize();   // g_scores complete

    for (int i = tid; i < MEM; i += 256) {
        const size_t idx = (size_t)b * MEM + i;
        const float s = g_scores[idx];
        const float sv = (s >= 0.0f) ? s : 0.01f * s;
        int lab = is64 ? lab32[2 * idx] : lab32[idx];
        lab = min(max(lab, 0), NCLS - 1);
        atomicAdd(&logits[lab], sv);
    }
    __syncthreads();

    // --- max ---
    float mx = -CUDART_INF_F;
    for (int i = tid; i < NCLS; i += 256) mx = fmaxf(mx, logits[i]);
    #pragma unroll
    for (int o = 16; o > 0; o >>= 1) mx = fmaxf(mx, __shfl_xor_sync(0xffffffffu, mx, o));
    if ((tid & 31) == 0) red[tid >> 5] = mx;
    __syncthreads();
    if (tid < 32) {
        float v = (tid < 8) ? red[tid] : -CUDART_INF_F;
        #pragma unroll
        for (int o = 4; o > 0; o >>= 1) v = fmaxf(v, __shfl_xor_sync(0xffffffffu, v, o));
        if (tid == 0) red[0] = v;
    }
    __syncthreads();
    mx = red[0];
    __syncthreads();

    // --- exp + sum ---
    float sum = 0.0f;
    for (int i = tid; i < NCLS; i += 256) {
        const float e = __expf(logits[i] - mx);
        logits[i] = e;
        sum += e;
    }
    #pragma unroll
    for (int o = 16; o > 0; o >>= 1) sum += __shfl_xor_sync(0xffffffffu, sum, o);
    if ((tid & 31) == 0) red[tid >> 5] = sum;
    __syncthreads();
    if (tid < 32) {
        float v = (tid < 8) ? red[tid] : 0.0f;
        #pragma unroll
        for (int o = 4; o > 0; o >>= 1) v += __shfl_xor_sync(0xffffffffu, v, o);
        if (tid == 0) red[0] = v;
    }
    __syncthreads();
    const float inv = 1.0f / red[0];

    for (int i = tid; i < NCLS; i += 256) out[b * NCLS + i] = logits[i] * inv;
}

// ---------------------------------------------------------------------------
// Launch (4 nodes): gemm1(+zero scores) -> gemm2 (PDL) -> score (PDL) ->
// epilogue (PDL). gemm1 launches plainly so it serializes with the previous
// replay's readers of g_qp/g_scores.
// Inputs mapped by element count: x 49152, mem 100663296, labels 131072,
// W_Q / W_K 589824 each (W_Q first).  Output: f32[64,1000].
// ---------------------------------------------------------------------------
template <typename... Args>
static inline void launch_pdl(void (*kern)(Args...), dim3 grid, dim3 block,
                              Args... args) {
    cudaLaunchConfig_t cfg = {};
    cfg.gridDim = grid;
    cfg.blockDim = block;
    cfg.dynamicSmemBytes = 0;
    cfg.stream = 0;
    cudaLaunchAttribute attr[1];
    attr[0].id = cudaLaunchAttributeProgrammaticStreamSerialization;
    attr[0].val.programmaticStreamSerializationAllowed = 1;
    cfg.attrs = attr;
    cfg.numAttrs = 1;
    cudaLaunchKernelEx(&cfg, kern, args...);
}

extern "C" void kernel_launch(void* const* d_in, const int* in_sizes, int n_in,
                              void* d_out, int out_size) {
    const float* x   = nullptr;
    const float* mem = nullptr;
    const int* labs  = nullptr;
    const float* W_Q = nullptr;
    const float* W_K = nullptr;

    for (int i = 0; i < n_in; i++) {
        const int sz = in_sizes[i];
        if (sz == BATCH * DIM)            x    = (const float*)d_in[i];
        else if (sz == BATCH * DIM * MEM) mem  = (const float*)d_in[i];
        else if (sz == BATCH * MEM)       labs = (const int*)d_in[i];
        else if (sz == DIM * DIM) {
            if (!W_Q) W_Q = (const float*)d_in[i];
            else      W_K = (const float*)d_in[i];
        }
    }
    float* out = (float*)d_out;

    gemm_partial<<<GEMM_BLOCKS + ZERO_BLOCKS, 256>>>(x, W_K, 0);  // q partials + zero scores
    launch_pdl(gemm_partial, dim3(GEMM_BLOCKS), dim3(256), (const float*)nullptr, W_Q, 1);
    launch_pdl(score_partial, dim3(2, NEC, BATCH), dim3(256), mem);
    launch_pdl(epilogue, dim3(BATCH), dim3(256), labs, out);
}